// round 4
// baseline (speedup 1.0000x reference)
#include <cuda_runtime.h>
#include <cstdint>
#include <math.h>

#define BB 32
#define TT 2048
#define FF 64
#define HH 256
#define GG 768
#define MTOT (BB*TT)

typedef unsigned long long u64;

// scratch (static device arrays: the sanctioned no-alloc workaround)
__device__ float g_xn[(size_t)MTOT*FF];
__device__ float g_xb[(size_t)MTOT*GG];
__device__ float g_h1[(size_t)MTOT*HH];
__device__ float g_h2[BB*HH];

__device__ __forceinline__ u64 ffma2(u64 a, u64 b, u64 c) {
    u64 d;
    asm("fma.rn.f32x2 %0, %1, %2, %3;" : "=l"(d) : "l"(a), "l"(b), "l"(c));
    return d;
}
__device__ __forceinline__ u64 pack2(float x, float y) {
    u64 d;
    asm("mov.b64 %0, {%1, %2};" : "=l"(d) : "f"(x), "f"(y));
    return d;
}
__device__ __forceinline__ void unpack2(u64 v, float& lo, float& hi) {
    asm("mov.b64 {%0, %1}, %2;" : "=f"(lo), "=f"(hi) : "l"(v));
}

// ---------------- LayerNorm: one warp per 64-feature row ----------------
__global__ void __launch_bounds__(256) ln_kernel(const float* __restrict__ x,
        const float* __restrict__ gamma, const float* __restrict__ beta,
        float* __restrict__ xn)
{
    int row  = blockIdx.x * 8 + (threadIdx.x >> 5);
    int lane = threadIdx.x & 31;
    const float* xr = x + (size_t)row * FF;
    float v0 = xr[lane], v1 = xr[lane + 32];
    float s = v0 + v1;
    #pragma unroll
    for (int o = 16; o > 0; o >>= 1) s += __shfl_xor_sync(0xffffffffu, s, o);
    float mu = s * (1.f / FF);
    float d0 = v0 - mu, d1 = v1 - mu;
    float q = d0 * d0 + d1 * d1;
    #pragma unroll
    for (int o = 16; o > 0; o >>= 1) q += __shfl_xor_sync(0xffffffffu, q, o);
    float inv = rsqrtf(q * (1.f / FF) + 1e-3f);
    float* orow = xn + (size_t)row * FF;
    orow[lane]      = d0 * inv * gamma[lane]      + beta[lane];
    orow[lane + 32] = d1 * inv * gamma[lane + 32] + beta[lane + 32];
}

// ---- GEMM + bias: C[M,N]=A@B+bias. 128x128 tile, BK=16, 8x8 microtile,
// ---- packed f32x2 FMA.
__global__ void __launch_bounds__(256) gemm_bias(const float* __restrict__ A,
        const float* __restrict__ B, const float* __restrict__ bias,
        float* __restrict__ C, int M, int N, int K)
{
    __shared__ __align__(16) float As[16][132];
    __shared__ __align__(16) float Bs[16][128];
    const int tid = threadIdx.x;
    const int bn = blockIdx.x * 128, bm = blockIdx.y * 128;
    const int arow = tid >> 2, ak = (tid & 3) << 2;
    const int brow = tid >> 4, bc = (tid & 15) << 3;
    const int rm   = (tid >> 4) << 3, rn = (tid & 15) << 3;

    u64 c2[8][4];
    #pragma unroll
    for (int i = 0; i < 8; ++i)
        #pragma unroll
        for (int j = 0; j < 4; ++j) c2[i][j] = 0ull;

    for (int k0 = 0; k0 < K; k0 += 16) {
        float4 a0 = *(const float4*)(A + (size_t)(bm + arow) * K + k0 + ak);
        float4 a1 = *(const float4*)(A + (size_t)(bm + arow + 64) * K + k0 + ak);
        As[ak + 0][arow] = a0.x; As[ak + 1][arow] = a0.y;
        As[ak + 2][arow] = a0.z; As[ak + 3][arow] = a0.w;
        As[ak + 0][arow + 64] = a1.x; As[ak + 1][arow + 64] = a1.y;
        As[ak + 2][arow + 64] = a1.z; As[ak + 3][arow + 64] = a1.w;
        *(float4*)&Bs[brow][bc]     = *(const float4*)(B + (size_t)(k0 + brow) * N + bn + bc);
        *(float4*)&Bs[brow][bc + 4] = *(const float4*)(B + (size_t)(k0 + brow) * N + bn + bc + 4);
        __syncthreads();
        #pragma unroll
        for (int k = 0; k < 16; ++k) {
            float4 x0 = *(const float4*)&As[k][rm];
            float4 x1 = *(const float4*)&As[k][rm + 4];
            ulonglong2 q0 = *(const ulonglong2*)&Bs[k][rn];
            ulonglong2 q1 = *(const ulonglong2*)&Bs[k][rn + 4];
            float am[8] = {x0.x, x0.y, x0.z, x0.w, x1.x, x1.y, x1.z, x1.w};
            #pragma unroll
            for (int i = 0; i < 8; ++i) {
                u64 aa = pack2(am[i], am[i]);
                c2[i][0] = ffma2(aa, q0.x, c2[i][0]);
                c2[i][1] = ffma2(aa, q0.y, c2[i][1]);
                c2[i][2] = ffma2(aa, q1.x, c2[i][2]);
                c2[i][3] = ffma2(aa, q1.y, c2[i][3]);
            }
        }
        __syncthreads();
    }
    float4 bv0 = *(const float4*)(bias + bn + rn);
    float4 bv1 = *(const float4*)(bias + bn + rn + 4);
    #pragma unroll
    for (int i = 0; i < 8; ++i) {
        float o[8];
        unpack2(c2[i][0], o[0], o[1]);
        unpack2(c2[i][1], o[2], o[3]);
        unpack2(c2[i][2], o[4], o[5]);
        unpack2(c2[i][3], o[6], o[7]);
        float4 w0 = {o[0] + bv0.x, o[1] + bv0.y, o[2] + bv0.z, o[3] + bv0.w};
        float4 w1 = {o[4] + bv1.x, o[5] + bv1.y, o[6] + bv1.z, o[7] + bv1.w};
        float* cp = C + (size_t)(bm + rm + i) * N + bn + rn;
        *(float4*)cp = w0;
        *(float4*)(cp + 4) = w1;
    }
}

// --------- Persistent GRU: 32 clusters x 4 CTAs, 1 cluster/batch ---------
// CTA rank owns h-cols [64r,64r+64) -> gate cols {j, 256+j, 512+j}.
// rk slice 256x192 fp32 in SMEM; h double-buffered; DSMEM push.
// Split cluster barrier: arrive at step end, wait deferred past the LOCAL
// k-block of the next step's matvec (hides barrier + peer-skew latency).
#define GRU_SMEM_FLOATS (49152 + 512 + 1536 + 192 + 192)
__global__ void __launch_bounds__(256, 1) __cluster_dims__(4, 1, 1)
gru_kernel(const float* __restrict__ xb, const float* __restrict__ rk,
           const float* __restrict__ brec, float* __restrict__ seqout,
           float* __restrict__ hfinal, int write_seq)
{
    extern __shared__ float sm[];
    float* wsm  = sm;              // [k=256][g=3][j=64]
    float* hsm  = wsm + 49152;     // 2 x 256
    float* red  = hsm + 512;       // [8 warps][16 kgrp][12]
    float* gate = red + 1536;      // [3][64]
    float* brs  = gate + 192;      // [3][64]

    const int tid   = threadIdx.x;
    const int rank  = blockIdx.x & 3;
    const int batch = blockIdx.x >> 2;
    const int jbase = rank * 64;

    for (int e = tid; e < 49152; e += 256) {
        int j = e & 63, g = (e >> 6) % 3, k = e / 192;
        wsm[e] = rk[(size_t)k * GG + g * 256 + jbase + j];
    }
    if (tid < 192) brs[tid] = brec[(tid >> 6) * 256 + jbase + (tid & 63)];
    hsm[tid] = 0.f; hsm[256 + tid] = 0.f;

    // precompute remote peer addresses for both h buffers
    uint32_t rem[2][3];
    if (tid < 64) {
        #pragma unroll
        for (int b = 0; b < 2; ++b) {
            uint32_t la = (uint32_t)__cvta_generic_to_shared(hsm + b * 256 + jbase + tid);
            #pragma unroll
            for (int p = 0; p < 3; ++p) {
                uint32_t tr = (uint32_t)((rank + 1 + p) & 3);
                asm("mapa.shared::cluster.u32 %0, %1, %2;"
                    : "=r"(rem[b][p]) : "r"(la), "r"(tr));
            }
        }
    }
    __syncthreads();
    // init sync: h buffers zeroed in every CTA before any peer DSMEM store
    asm volatile("barrier.cluster.arrive.aligned;" ::: "memory");
    asm volatile("barrier.cluster.wait.aligned;" ::: "memory");

    const int c4   = (tid & 15) * 4;
    const int ksub = (tid >> 4) * 4;   // 4 k's per 64-block per thread
    const int warp = tid >> 5;
    const bool lo  = (tid & 31) < 16;
    const float* xrow = xb + (size_t)batch * TT * GG;
    float* srow = seqout + (size_t)batch * TT * HH;

#define MV_BLOCK(blk) { \
        int kb = (blk) * 64 + ksub; \
        float4 h4 = *(const float4*)(cur + kb); \
        float hv4[4] = {h4.x, h4.y, h4.z, h4.w}; \
        _Pragma("unroll") \
        for (int u = 0; u < 4; ++u) { \
            const float* w = wsm + (kb + u) * 192 + c4; \
            float hv = hv4[u]; \
            float4 wz = *(const float4*)(w); \
            float4 wr = *(const float4*)(w + 64); \
            float4 wh = *(const float4*)(w + 128); \
            a[0]+=hv*wz.x; a[1]+=hv*wz.y; a[2] +=hv*wz.z; a[3] +=hv*wz.w; \
            a[4]+=hv*wr.x; a[5]+=hv*wr.y; a[6] +=hv*wr.z; a[7] +=hv*wr.w; \
            a[8]+=hv*wh.x; a[9]+=hv*wh.y; a[10]+=hv*wh.z; a[11]+=hv*wh.w; \
        } }

    for (int t = 0; t < TT; ++t) {
        const float* cur = hsm + ((t & 1) << 8);
        float*       nxt = hsm + (((t & 1) ^ 1) << 8);
        const int    nb  = (t & 1) ^ 1;

        float xz = 0.f, xr_ = 0.f, xh = 0.f;
        if (tid < 64) {
            const float* xp = xrow + (size_t)t * GG + jbase + tid;
            xz = __ldg(xp); xr_ = __ldg(xp + 256); xh = __ldg(xp + 512);
        }

        float a[12];
        #pragma unroll
        for (int v = 0; v < 12; ++v) a[v] = 0.f;

        // phase 1: local k-block (own CTA's h slice; no peer dependency)
        MV_BLOCK(rank)
        // now require peers' step-(t-1) h values (released by their arrive)
        if (t > 0)
            asm volatile("barrier.cluster.wait.aligned;" ::: "memory");
        // phase 2: the three remote k-blocks
        #pragma unroll
        for (int rr = 1; rr < 4; ++rr) MV_BLOCK((rank + rr) & 3)

        #pragma unroll
        for (int v = 0; v < 12; ++v) a[v] += __shfl_xor_sync(0xffffffffu, a[v], 16);
        if (lo) {
            float* r = red + (warp * 16 + (tid & 15)) * 12;
            #pragma unroll
            for (int v = 0; v < 12; ++v) r[v] = a[v];
        }
        __syncthreads();
        if (tid < 192) {
            int cc = tid / 12, v = tid - cc * 12;
            float s = 0.f;
            #pragma unroll
            for (int w8 = 0; w8 < 8; ++w8) s += red[(w8 * 16 + cc) * 12 + v];
            gate[(v >> 2) * 64 + cc * 4 + (v & 3)] = s;
        }
        __syncthreads();
        if (tid < 64) {
            float gz = gate[tid]       + brs[tid]       + xz;
            float gr = gate[64 + tid]  + brs[64 + tid]  + xr_;
            float gh = gate[128 + tid] + brs[128 + tid];
            float z  = 1.f / (1.f + expf(-gz));
            float r  = 1.f / (1.f + expf(-gr));
            float hh = tanhf(xh + r * gh);
            float hp = cur[jbase + tid];
            float hn = z * hp + (1.f - z) * hh;
            nxt[jbase + tid] = hn;
            #pragma unroll
            for (int p = 0; p < 3; ++p)
                asm volatile("st.shared::cluster.f32 [%0], %1;"
                             :: "r"(rem[nb][p]), "f"(hn) : "memory");
            if (write_seq) srow[(size_t)t * HH + jbase + tid] = hn;
        }
        __syncthreads();   // own nxt slice visible CTA-wide before arrive
        asm volatile("barrier.cluster.arrive.aligned;" ::: "memory");
    }
    // pair the final arrive; also guarantees no peer still targets our SMEM
    asm volatile("barrier.cluster.wait.aligned;" ::: "memory");
    if (!write_seq && tid < 64)
        hfinal[batch * HH + jbase + tid] = hsm[((TT & 1)) * 256 + jbase + tid];
#undef MV_BLOCK
}

// ---------------- Dense: out[32,64] = h2 @ wd + bd ----------------
__global__ void __launch_bounds__(256) dense_kernel(const float* __restrict__ h2,
        const float* __restrict__ wd, const float* __restrict__ bd,
        float* __restrict__ out)
{
    int o = blockIdx.x * 256 + threadIdx.x;
    int b = o >> 6, j = o & 63;
    float s = bd[j];
    for (int k = 0; k < HH; ++k) s += h2[b * HH + k] * wd[k * 64 + j];
    out[o] = s;
}

extern "C" void kernel_launch(void* const* d_in, const int* in_sizes, int n_in,
                              void* d_out, int out_size) {
    const float* x     = (const float*)d_in[0];
    const float* gamma = (const float*)d_in[1];
    const float* beta  = (const float*)d_in[2];
    const float* k1    = (const float*)d_in[3];
    const float* rk1   = (const float*)d_in[4];
    const float* b1    = (const float*)d_in[5];
    const float* k2    = (const float*)d_in[6];
    const float* rk2   = (const float*)d_in[7];
    const float* b2    = (const float*)d_in[8];
    const float* wd    = (const float*)d_in[9];
    const float* bd    = (const float*)d_in[10];
    float* out = (float*)d_out;

    float *xn, *xbuf, *h1, *h2;
    cudaGetSymbolAddress((void**)&xn,   g_xn);
    cudaGetSymbolAddress((void**)&xbuf, g_xb);
    cudaGetSymbolAddress((void**)&h1,   g_h1);
    cudaGetSymbolAddress((void**)&h2,   g_h2);

    cudaFuncSetAttribute(gru_kernel, cudaFuncAttributeMaxDynamicSharedMemorySize,
                         GRU_SMEM_FLOATS * 4);

    ln_kernel<<<MTOT / 8, 256>>>(x, gamma, beta, xn);
    gemm_bias<<<dim3(GG / 128, MTOT / 128), 256>>>(xn, k1, b1, xbuf, MTOT, GG, FF);
    gru_kernel<<<128, 256, GRU_SMEM_FLOATS * 4>>>(xbuf, rk1, b1 + GG, h1, h2, 1);
    gemm_bias<<<dim3(GG / 128, MTOT / 128), 256>>>(h1, k2, b2, xbuf, MTOT, GG, HH);
    gru_kernel<<<128, 256, GRU_SMEM_FLOATS * 4>>>(xbuf, rk2, b2 + GG, h1, h2, 0);
    dense_kernel<<<(BB * 64) / 256, 256>>>(h2, wd, bd, out);
}

// round 5
// speedup vs baseline: 1.4080x; 1.4080x over previous
#include <cuda_runtime.h>
#include <cstdint>
#include <math.h>

#define BB 32
#define TT 2048
#define FF 64
#define HH 256
#define GG 768
#define MTOT (BB*TT)

typedef unsigned long long u64;

// scratch (static device arrays: the sanctioned no-alloc workaround)
__device__ float g_xn[(size_t)MTOT*FF];
__device__ float g_xb[(size_t)MTOT*GG];
__device__ float g_h1[(size_t)MTOT*HH];
__device__ float g_h2[BB*HH];

__device__ __forceinline__ u64 ffma2(u64 a, u64 b, u64 c) {
    u64 d;
    asm("fma.rn.f32x2 %0, %1, %2, %3;" : "=l"(d) : "l"(a), "l"(b), "l"(c));
    return d;
}
__device__ __forceinline__ u64 pack2(float x, float y) {
    u64 d;
    asm("mov.b64 %0, {%1, %2};" : "=l"(d) : "f"(x), "f"(y));
    return d;
}
__device__ __forceinline__ void unpack2(u64 v, float& lo, float& hi) {
    asm("mov.b64 {%0, %1}, %2;" : "=f"(lo), "=f"(hi) : "l"(v));
}

// ---------------- LayerNorm: one warp per 64-feature row ----------------
__global__ void __launch_bounds__(256) ln_kernel(const float* __restrict__ x,
        const float* __restrict__ gamma, const float* __restrict__ beta,
        float* __restrict__ xn)
{
    int row  = blockIdx.x * 8 + (threadIdx.x >> 5);
    int lane = threadIdx.x & 31;
    const float* xr = x + (size_t)row * FF;
    float v0 = xr[lane], v1 = xr[lane + 32];
    float s = v0 + v1;
    #pragma unroll
    for (int o = 16; o > 0; o >>= 1) s += __shfl_xor_sync(0xffffffffu, s, o);
    float mu = s * (1.f / FF);
    float d0 = v0 - mu, d1 = v1 - mu;
    float q = d0 * d0 + d1 * d1;
    #pragma unroll
    for (int o = 16; o > 0; o >>= 1) q += __shfl_xor_sync(0xffffffffu, q, o);
    float inv = rsqrtf(q * (1.f / FF) + 1e-3f);
    float* orow = xn + (size_t)row * FF;
    orow[lane]      = d0 * inv * gamma[lane]      + beta[lane];
    orow[lane + 32] = d1 * inv * gamma[lane + 32] + beta[lane + 32];
}

// ---- GEMM + bias: C[M,N]=A@B+bias. 128x128 tile, BK=16, 8x8 microtile,
// ---- packed f32x2 FMA. (unchanged from R4: 581us measured)
__global__ void __launch_bounds__(256) gemm_bias(const float* __restrict__ A,
        const float* __restrict__ B, const float* __restrict__ bias,
        float* __restrict__ C, int M, int N, int K)
{
    __shared__ __align__(16) float As[16][132];
    __shared__ __align__(16) float Bs[16][128];
    const int tid = threadIdx.x;
    const int bn = blockIdx.x * 128, bm = blockIdx.y * 128;
    const int arow = tid >> 2, ak = (tid & 3) << 2;
    const int brow = tid >> 4, bc = (tid & 15) << 3;
    const int rm   = (tid >> 4) << 3, rn = (tid & 15) << 3;

    u64 c2[8][4];
    #pragma unroll
    for (int i = 0; i < 8; ++i)
        #pragma unroll
        for (int j = 0; j < 4; ++j) c2[i][j] = 0ull;

    for (int k0 = 0; k0 < K; k0 += 16) {
        float4 a0 = *(const float4*)(A + (size_t)(bm + arow) * K + k0 + ak);
        float4 a1 = *(const float4*)(A + (size_t)(bm + arow + 64) * K + k0 + ak);
        As[ak + 0][arow] = a0.x; As[ak + 1][arow] = a0.y;
        As[ak + 2][arow] = a0.z; As[ak + 3][arow] = a0.w;
        As[ak + 0][arow + 64] = a1.x; As[ak + 1][arow + 64] = a1.y;
        As[ak + 2][arow + 64] = a1.z; As[ak + 3][arow + 64] = a1.w;
        *(float4*)&Bs[brow][bc]     = *(const float4*)(B + (size_t)(k0 + brow) * N + bn + bc);
        *(float4*)&Bs[brow][bc + 4] = *(const float4*)(B + (size_t)(k0 + brow) * N + bn + bc + 4);
        __syncthreads();
        #pragma unroll
        for (int k = 0; k < 16; ++k) {
            float4 x0 = *(const float4*)&As[k][rm];
            float4 x1 = *(const float4*)&As[k][rm + 4];
            ulonglong2 q0 = *(const ulonglong2*)&Bs[k][rn];
            ulonglong2 q1 = *(const ulonglong2*)&Bs[k][rn + 4];
            float am[8] = {x0.x, x0.y, x0.z, x0.w, x1.x, x1.y, x1.z, x1.w};
            #pragma unroll
            for (int i = 0; i < 8; ++i) {
                u64 aa = pack2(am[i], am[i]);
                c2[i][0] = ffma2(aa, q0.x, c2[i][0]);
                c2[i][1] = ffma2(aa, q0.y, c2[i][1]);
                c2[i][2] = ffma2(aa, q1.x, c2[i][2]);
                c2[i][3] = ffma2(aa, q1.y, c2[i][3]);
            }
        }
        __syncthreads();
    }
    float4 bv0 = *(const float4*)(bias + bn + rn);
    float4 bv1 = *(const float4*)(bias + bn + rn + 4);
    #pragma unroll
    for (int i = 0; i < 8; ++i) {
        float o[8];
        unpack2(c2[i][0], o[0], o[1]);
        unpack2(c2[i][1], o[2], o[3]);
        unpack2(c2[i][2], o[4], o[5]);
        unpack2(c2[i][3], o[6], o[7]);
        float4 w0 = {o[0] + bv0.x, o[1] + bv0.y, o[2] + bv0.z, o[3] + bv0.w};
        float4 w1 = {o[4] + bv1.x, o[5] + bv1.y, o[6] + bv1.z, o[7] + bv1.w};
        float* cp = C + (size_t)(bm + rm + i) * N + bn + rn;
        *(float4*)cp = w0;
        *(float4*)(cp + 4) = w1;
    }
}

// --------- Persistent GRU: 32 clusters x 4 CTAs, 1 cluster/batch ---------
// REGISTER-RESIDENT weights: each thread holds its 16k x 12col slice as
// 96 packed f32x2 regs, phase-ordered (phase p = k-block (rank+p)&3) so all
// register indices are compile-time. Matvec = 96 ffma2/thread/step.
// Phase 0 (own block) runs before the cluster wait to hide barrier latency.
__global__ void __launch_bounds__(256, 1) __cluster_dims__(4, 1, 1)
gru_kernel(const float* __restrict__ xb, const float* __restrict__ rk,
           const float* __restrict__ brec, float* __restrict__ seqout,
           float* __restrict__ hfinal, int write_seq)
{
    __shared__ float hsm[512];        // 2 x 256 double-buffered h
    __shared__ float red[1536];       // [8 warps][16 kgrp][12]
    __shared__ float gate[192];       // [3][64]
    __shared__ float brs[192];        // [3][64]

    const int tid   = threadIdx.x;
    const int rank  = blockIdx.x & 3;
    const int batch = blockIdx.x >> 2;
    const int jbase = rank * 64;
    const int c4    = (tid & 15) * 4;
    const int ksub  = (tid >> 4) * 4;
    const int warp  = tid >> 5;
    const bool lo   = (tid & 31) < 16;

    // k-block base per phase: phase 0 = own block
    int blk[4];
    #pragma unroll
    for (int p = 0; p < 4; ++p) blk[p] = (((rank + p) & 3)) * 64;

    // load weights into registers, phase-ordered, column-paired (f32x2)
    u64 w2[16][6];
    #pragma unroll
    for (int p = 0; p < 4; ++p)
        #pragma unroll
        for (int u = 0; u < 4; ++u) {
            const float* wp = rk + (size_t)(blk[p] + ksub + u) * GG;
            #pragma unroll
            for (int g = 0; g < 3; ++g) {
                float4 v = *(const float4*)(wp + g * 256 + jbase + c4);
                w2[p * 4 + u][g * 2 + 0] = pack2(v.x, v.y);
                w2[p * 4 + u][g * 2 + 1] = pack2(v.z, v.w);
            }
        }

    if (tid < 192) brs[tid] = brec[(tid >> 6) * 256 + jbase + (tid & 63)];
    hsm[tid] = 0.f; hsm[256 + tid] = 0.f;
    __syncthreads();
    asm volatile("barrier.cluster.arrive.aligned;" ::: "memory");
    asm volatile("barrier.cluster.wait.aligned;" ::: "memory");

    const float* xrow = xb + (size_t)batch * TT * GG;
    float* srow = seqout + (size_t)batch * TT * HH;

#define MV_PHASE(p) { \
        float4 h4 = *(const float4*)(cur + blk[p] + ksub); \
        float hv[4] = {h4.x, h4.y, h4.z, h4.w}; \
        _Pragma("unroll") \
        for (int u = 0; u < 4; ++u) { \
            u64 hp = pack2(hv[u], hv[u]); \
            _Pragma("unroll") \
            for (int v = 0; v < 6; ++v) \
                a2[v] = ffma2(hp, w2[(p) * 4 + u][v], a2[v]); \
        } }

    for (int t = 0; t < TT; ++t) {
        const float* cur = hsm + ((t & 1) << 8);
        float*       nxt = hsm + (((t & 1) ^ 1) << 8);

        float xz = 0.f, xr_ = 0.f, xh = 0.f;
        if (tid < 64) {
            const float* xp = xrow + (size_t)t * GG + jbase + tid;
            xz = __ldg(xp); xr_ = __ldg(xp + 256); xh = __ldg(xp + 512);
        }

        u64 a2[6];
        #pragma unroll
        for (int v = 0; v < 6; ++v) a2[v] = 0ull;

        // phase 0: own k-block (ordered by last step's __syncthreads)
        MV_PHASE(0)
        if (t > 0)
            asm volatile("barrier.cluster.wait.aligned;" ::: "memory");
        MV_PHASE(1)
        MV_PHASE(2)
        MV_PHASE(3)

        float a[12];
        #pragma unroll
        for (int v = 0; v < 6; ++v) unpack2(a2[v], a[2 * v], a[2 * v + 1]);
        #pragma unroll
        for (int v = 0; v < 12; ++v) a[v] += __shfl_xor_sync(0xffffffffu, a[v], 16);
        if (lo) {
            float* r = red + (warp * 16 + (tid & 15)) * 12;
            #pragma unroll
            for (int v = 0; v < 12; ++v) r[v] = a[v];
        }
        __syncthreads();
        if (tid < 192) {
            int cc = tid / 12, v = tid - cc * 12;
            float s = 0.f;
            #pragma unroll
            for (int w8 = 0; w8 < 8; ++w8) s += red[(w8 * 16 + cc) * 12 + v];
            gate[(v >> 2) * 64 + cc * 4 + (v & 3)] = s;
        }
        __syncthreads();
        if (tid < 64) {
            float gz = gate[tid]       + brs[tid]       + xz;
            float gr = gate[64 + tid]  + brs[64 + tid]  + xr_;
            float gh = gate[128 + tid] + brs[128 + tid];
            float z  = 1.f / (1.f + expf(-gz));
            float r  = 1.f / (1.f + expf(-gr));
            float hh = tanhf(xh + r * gh);
            float hp = cur[jbase + tid];
            float hn = z * hp + (1.f - z) * hh;
            nxt[jbase + tid] = hn;
            uint32_t la = (uint32_t)__cvta_generic_to_shared(nxt + jbase + tid);
            #pragma unroll
            for (int p = 1; p < 4; ++p) {
                uint32_t ra, tr = (uint32_t)((rank + p) & 3);
                asm("mapa.shared::cluster.u32 %0, %1, %2;" : "=r"(ra) : "r"(la), "r"(tr));
                asm volatile("st.shared::cluster.f32 [%0], %1;" :: "r"(ra), "f"(hn) : "memory");
            }
            if (write_seq) srow[(size_t)t * HH + jbase + tid] = hn;
        }
        __syncthreads();   // local nxt slice visible CTA-wide before phase-0 read
        asm volatile("barrier.cluster.arrive.aligned;" ::: "memory");
    }
    asm volatile("barrier.cluster.wait.aligned;" ::: "memory");
    if (!write_seq && tid < 64)
        hfinal[batch * HH + jbase + tid] = hsm[(TT & 1) * 256 + jbase + tid];
#undef MV_PHASE
}

// ---------------- Dense: out[32,64] = h2 @ wd + bd ----------------
__global__ void __launch_bounds__(256) dense_kernel(const float* __restrict__ h2,
        const float* __restrict__ wd, const float* __restrict__ bd,
        float* __restrict__ out)
{
    int o = blockIdx.x * 256 + threadIdx.x;
    int b = o >> 6, j = o & 63;
    float s = bd[j];
    for (int k = 0; k < HH; ++k) s += h2[b * HH + k] * wd[k * 64 + j];
    out[o] = s;
}

extern "C" void kernel_launch(void* const* d_in, const int* in_sizes, int n_in,
                              void* d_out, int out_size) {
    const float* x     = (const float*)d_in[0];
    const float* gamma = (const float*)d_in[1];
    const float* beta  = (const float*)d_in[2];
    const float* k1    = (const float*)d_in[3];
    const float* rk1   = (const float*)d_in[4];
    const float* b1    = (const float*)d_in[5];
    const float* k2    = (const float*)d_in[6];
    const float* rk2   = (const float*)d_in[7];
    const float* b2    = (const float*)d_in[8];
    const float* wd    = (const float*)d_in[9];
    const float* bd    = (const float*)d_in[10];
    float* out = (float*)d_out;

    float *xn, *xbuf, *h1, *h2;
    cudaGetSymbolAddress((void**)&xn,   g_xn);
    cudaGetSymbolAddress((void**)&xbuf, g_xb);
    cudaGetSymbolAddress((void**)&h1,   g_h1);
    cudaGetSymbolAddress((void**)&h2,   g_h2);

    ln_kernel<<<MTOT / 8, 256>>>(x, gamma, beta, xn);
    gemm_bias<<<dim3(GG / 128, MTOT / 128), 256>>>(xn, k1, b1, xbuf, MTOT, GG, FF);
    gru_kernel<<<128, 256>>>(xbuf, rk1, b1 + GG, h1, h2, 1);
    gemm_bias<<<dim3(GG / 128, MTOT / 128), 256>>>(h1, k2, b2, xbuf, MTOT, GG, HH);
    gru_kernel<<<128, 256>>>(xbuf, rk2, b2 + GG, h1, h2, 0);
    dense_kernel<<<(BB * 64) / 256, 256>>>(h2, wd, bd, out);
}

// round 6
// speedup vs baseline: 1.8714x; 1.3291x over previous
#include <cuda_runtime.h>
#include <cstdint>
#include <math.h>

#define BB 32
#define TT 2048
#define FF 64
#define HH 256
#define GG 768
#define MTOT (BB*TT)

typedef unsigned long long u64;

// scratch (static device arrays: the sanctioned no-alloc workaround)
__device__ float g_xn[(size_t)MTOT*FF];
__device__ float g_xb[(size_t)MTOT*GG];
__device__ float g_h1[(size_t)MTOT*HH];
__device__ float g_h2[BB*HH];

__device__ __forceinline__ u64 ffma2(u64 a, u64 b, u64 c) {
    u64 d;
    asm("fma.rn.f32x2 %0, %1, %2, %3;" : "=l"(d) : "l"(a), "l"(b), "l"(c));
    return d;
}
__device__ __forceinline__ u64 addf2(u64 a, u64 b) {
    u64 d;
    asm("add.rn.f32x2 %0, %1, %2;" : "=l"(d) : "l"(a), "l"(b));
    return d;
}
__device__ __forceinline__ u64 pack2(float x, float y) {
    u64 d;
    asm("mov.b64 %0, {%1, %2};" : "=l"(d) : "f"(x), "f"(y));
    return d;
}
__device__ __forceinline__ void unpack2(u64 v, float& lo, float& hi) {
    asm("mov.b64 {%0, %1}, %2;" : "=f"(lo), "=f"(hi) : "l"(v));
}
__device__ __forceinline__ uint32_t smem_u32(const void* p) {
    return (uint32_t)__cvta_generic_to_shared(p);
}

#define MBAR_INIT(addr, cnt) \
    asm volatile("mbarrier.init.shared.b64 [%0], %1;" :: "r"(addr), "r"(cnt) : "memory")
#define MBAR_EXPECT_TX(addr, bytes) \
    asm volatile("mbarrier.arrive.expect_tx.shared.b64 _, [%0], %1;" :: "r"(addr), "r"(bytes) : "memory")
#define MBAR_WAIT_PARITY(addr, par) do { \
    uint32_t _done = 0; \
    while (!_done) { \
        asm volatile("{\n\t.reg .pred P;\n\t" \
            "mbarrier.try_wait.parity.acquire.cta.shared::cta.b64 P, [%1], %2, 0x989680;\n\t" \
            "selp.b32 %0, 1, 0, P;\n\t}" \
            : "=r"(_done) : "r"(addr), "r"(par) : "memory"); \
    } } while (0)
#define ST_ASYNC_F32(raddr, val, rbar) \
    asm volatile("st.async.shared::cluster.mbarrier::complete_tx::bytes.b32 [%0], %1, [%2];" \
        :: "r"(raddr), "r"(val), "r"(rbar) : "memory")

// ---------------- LayerNorm: one warp per 64-feature row ----------------
__global__ void __launch_bounds__(256) ln_kernel(const float* __restrict__ x,
        const float* __restrict__ gamma, const float* __restrict__ beta,
        float* __restrict__ xn)
{
    int row  = blockIdx.x * 8 + (threadIdx.x >> 5);
    int lane = threadIdx.x & 31;
    const float* xr = x + (size_t)row * FF;
    float v0 = xr[lane], v1 = xr[lane + 32];
    float s = v0 + v1;
    #pragma unroll
    for (int o = 16; o > 0; o >>= 1) s += __shfl_xor_sync(0xffffffffu, s, o);
    float mu = s * (1.f / FF);
    float d0 = v0 - mu, d1 = v1 - mu;
    float q = d0 * d0 + d1 * d1;
    #pragma unroll
    for (int o = 16; o > 0; o >>= 1) q += __shfl_xor_sync(0xffffffffu, q, o);
    float inv = rsqrtf(q * (1.f / FF) + 1e-3f);
    float* orow = xn + (size_t)row * FF;
    orow[lane]      = d0 * inv * gamma[lane]      + beta[lane];
    orow[lane + 32] = d1 * inv * gamma[lane + 32] + beta[lane + 32];
}

// ---- GEMM + bias: 128x128 tile, BK=16, 8x8 microtile, f32x2 FMA ----
__global__ void __launch_bounds__(256) gemm_bias(const float* __restrict__ A,
        const float* __restrict__ B, const float* __restrict__ bias,
        float* __restrict__ C, int M, int N, int K)
{
    __shared__ __align__(16) float As[16][132];
    __shared__ __align__(16) float Bs[16][128];
    const int tid = threadIdx.x;
    const int bn = blockIdx.x * 128, bm = blockIdx.y * 128;
    const int arow = tid >> 2, ak = (tid & 3) << 2;
    const int brow = tid >> 4, bc = (tid & 15) << 3;
    const int rm   = (tid >> 4) << 3, rn = (tid & 15) << 3;

    u64 c2[8][4];
    #pragma unroll
    for (int i = 0; i < 8; ++i)
        #pragma unroll
        for (int j = 0; j < 4; ++j) c2[i][j] = 0ull;

    for (int k0 = 0; k0 < K; k0 += 16) {
        float4 a0 = *(const float4*)(A + (size_t)(bm + arow) * K + k0 + ak);
        float4 a1 = *(const float4*)(A + (size_t)(bm + arow + 64) * K + k0 + ak);
        As[ak + 0][arow] = a0.x; As[ak + 1][arow] = a0.y;
        As[ak + 2][arow] = a0.z; As[ak + 3][arow] = a0.w;
        As[ak + 0][arow + 64] = a1.x; As[ak + 1][arow + 64] = a1.y;
        As[ak + 2][arow + 64] = a1.z; As[ak + 3][arow + 64] = a1.w;
        *(float4*)&Bs[brow][bc]     = *(const float4*)(B + (size_t)(k0 + brow) * N + bn + bc);
        *(float4*)&Bs[brow][bc + 4] = *(const float4*)(B + (size_t)(k0 + brow) * N + bn + bc + 4);
        __syncthreads();
        #pragma unroll
        for (int k = 0; k < 16; ++k) {
            float4 x0 = *(const float4*)&As[k][rm];
            float4 x1 = *(const float4*)&As[k][rm + 4];
            ulonglong2 q0 = *(const ulonglong2*)&Bs[k][rn];
            ulonglong2 q1 = *(const ulonglong2*)&Bs[k][rn + 4];
            float am[8] = {x0.x, x0.y, x0.z, x0.w, x1.x, x1.y, x1.z, x1.w};
            #pragma unroll
            for (int i = 0; i < 8; ++i) {
                u64 aa = pack2(am[i], am[i]);
                c2[i][0] = ffma2(aa, q0.x, c2[i][0]);
                c2[i][1] = ffma2(aa, q0.y, c2[i][1]);
                c2[i][2] = ffma2(aa, q1.x, c2[i][2]);
                c2[i][3] = ffma2(aa, q1.y, c2[i][3]);
            }
        }
        __syncthreads();
    }
    float4 bv0 = *(const float4*)(bias + bn + rn);
    float4 bv1 = *(const float4*)(bias + bn + rn + 4);
    #pragma unroll
    for (int i = 0; i < 8; ++i) {
        float o[8];
        unpack2(c2[i][0], o[0], o[1]);
        unpack2(c2[i][1], o[2], o[3]);
        unpack2(c2[i][2], o[4], o[5]);
        unpack2(c2[i][3], o[6], o[7]);
        float4 w0 = {o[0] + bv0.x, o[1] + bv0.y, o[2] + bv0.z, o[3] + bv0.w};
        float4 w1 = {o[4] + bv1.x, o[5] + bv1.y, o[6] + bv1.z, o[7] + bv1.w};
        float* cp = C + (size_t)(bm + rm + i) * N + bn + rn;
        *(float4*)cp = w0;
        *(float4*)(cp + 4) = w1;
    }
}

// --------- Persistent GRU: 32 clusters x 4 CTAs, 1 cluster/batch ---------
// Register-resident weights (96 u64/thread). Warp w owns k-slice w*8..w*8+8
// of each 64-k phase block; lane l owns column-pair {2l,2l+1} of each gate
// -> 3 packed accumulators, partials reduced once through smem.
// h exchange: st.async DSMEM pushes + 2 parity-alternating tx-mbarriers
// (no barrier.cluster in the loop). Phase 0 (own k-block) runs before the
// wait to hide push/wait latency.
__global__ void __launch_bounds__(256, 1) __cluster_dims__(4, 1, 1)
gru_kernel(const float* __restrict__ xb, const float* __restrict__ rk,
           const float* __restrict__ brec, float* __restrict__ seqout,
           float* __restrict__ hfinal, int write_seq)
{
    __shared__ __align__(16) float hsm[512];          // 2 x 256 h double-buffer
    __shared__ __align__(16) u64 red[768];            // [gate][warp][cg] = 3*8*32
    __shared__ float brs[192];                        // [3][64]
    __shared__ __align__(8) u64 mbars[2];             // step-parity tx barriers

    const int tid   = threadIdx.x;
    const int rank  = blockIdx.x & 3;
    const int batch = blockIdx.x >> 2;
    const int jbase = rank * 64;
    const int w     = tid >> 5;     // k-slice within each 64-block
    const int l     = tid & 31;     // column-pair group

    int blk[4];
    #pragma unroll
    for (int p = 0; p < 4; ++p) blk[p] = ((rank + p) & 3) * 64;

    // weights: w2[p*8+kk][g] = rk[blk[p]+w*8+kk][g*256 + jbase + {2l,2l+1}]
    u64 w2[32][3];
    #pragma unroll
    for (int p = 0; p < 4; ++p)
        #pragma unroll
        for (int kk = 0; kk < 8; ++kk) {
            const float* wp = rk + (size_t)(blk[p] + w * 8 + kk) * GG + jbase + 2 * l;
            #pragma unroll
            for (int g = 0; g < 3; ++g) {
                float2 v = *(const float2*)(wp + g * 256);
                w2[p * 8 + kk][g] = pack2(v.x, v.y);
            }
        }

    if (tid < 192) brs[tid] = brec[(tid >> 6) * 256 + jbase + (tid & 63)];
    hsm[tid] = 0.f; hsm[256 + tid] = 0.f;

    uint32_t mb[2] = { smem_u32(&mbars[0]), smem_u32(&mbars[1]) };
    if (tid == 0) { MBAR_INIT(mb[0], 1); MBAR_INIT(mb[1], 1); }

    // remote addresses: rem_h[buffer][peer] for my h element, rem_bar[bar][peer]
    uint32_t rem_h[2][3], rem_bar[2][3];
    if (tid < 64) {
        #pragma unroll
        for (int b = 0; b < 2; ++b) {
            uint32_t lh = smem_u32(hsm + b * 256 + jbase + tid);
            uint32_t lb = mb[b];
            #pragma unroll
            for (int p = 0; p < 3; ++p) {
                uint32_t tr = (uint32_t)((rank + 1 + p) & 3), rh, rb;
                asm("mapa.shared::cluster.u32 %0, %1, %2;" : "=r"(rh) : "r"(lh), "r"(tr));
                asm("mapa.shared::cluster.u32 %0, %1, %2;" : "=r"(rb) : "r"(lb), "r"(tr));
                rem_h[b][p] = rh; rem_bar[b][p] = rb;
            }
        }
    }
    __syncthreads();
    // barriers + zeroed h visible cluster-wide before any st.async
    asm volatile("barrier.cluster.arrive.aligned;" ::: "memory");
    asm volatile("barrier.cluster.wait.aligned;" ::: "memory");
    if (tid == 0) { MBAR_EXPECT_TX(mb[0], 768); MBAR_EXPECT_TX(mb[1], 768); } // steps 0,1

    const float* xrow = xb + (size_t)batch * TT * GG;
    float* srow = seqout + (size_t)batch * TT * HH;

#define MV_PHASE(p) { \
        float4 h4a = *(const float4*)(cur + blk[p] + w * 8); \
        float4 h4b = *(const float4*)(cur + blk[p] + w * 8 + 4); \
        float hv[8] = {h4a.x, h4a.y, h4a.z, h4a.w, h4b.x, h4b.y, h4b.z, h4b.w}; \
        _Pragma("unroll") \
        for (int kk = 0; kk < 8; ++kk) { \
            u64 hp = pack2(hv[kk], hv[kk]); \
            a2[0] = ffma2(hp, w2[(p) * 8 + kk][0], a2[0]); \
            a2[1] = ffma2(hp, w2[(p) * 8 + kk][1], a2[1]); \
            a2[2] = ffma2(hp, w2[(p) * 8 + kk][2], a2[2]); \
        } }

    for (int t = 0; t < TT; ++t) {
        const float* cur = hsm + ((t & 1) << 8);
        float*       nxt = hsm + (((t & 1) ^ 1) << 8);
        const int    nb  = (t & 1) ^ 1;

        float xz = 0.f, xr_ = 0.f, xh = 0.f;
        if (tid < 64) {
            const float* xp = xrow + (size_t)t * GG + jbase + tid;
            xz = __ldg(xp); xr_ = __ldg(xp + 256); xh = __ldg(xp + 512);
        }

        u64 a2[3] = {0ull, 0ull, 0ull};
        // phase 0: own k-block (local writes ordered by last step's syncthreads)
        MV_PHASE(0)
        if (t > 0) {
            // wait for step t-1 pushes: barrier (t-1)&1, phase (t-1)>>1
            MBAR_WAIT_PARITY(mb[(t - 1) & 1], ((t - 1) >> 1) & 1);
            if (tid == 0 && t <= TT - 3) MBAR_EXPECT_TX(mb[(t + 1) & 1], 768);
        }
        MV_PHASE(1)
        MV_PHASE(2)
        MV_PHASE(3)

        red[0 * 256 + w * 32 + l] = a2[0];
        red[1 * 256 + w * 32 + l] = a2[1];
        red[2 * 256 + w * 32 + l] = a2[2];
        __syncthreads();

        if (tid < 64) {
            const int cg = tid >> 1, half = tid & 1;
            u64 s0 = red[cg], s1 = red[256 + cg], s2 = red[512 + cg];
            #pragma unroll
            for (int ww = 1; ww < 8; ++ww) {
                s0 = addf2(s0, red[ww * 32 + cg]);
                s1 = addf2(s1, red[256 + ww * 32 + cg]);
                s2 = addf2(s2, red[512 + ww * 32 + cg]);
            }
            float lo0, hi0, lo1, hi1, lo2, hi2;
            unpack2(s0, lo0, hi0); unpack2(s1, lo1, hi1); unpack2(s2, lo2, hi2);
            float gz = (half ? hi0 : lo0) + brs[tid]       + xz;
            float gr = (half ? hi1 : lo1) + brs[64 + tid]  + xr_;
            float gh = (half ? hi2 : lo2) + brs[128 + tid];
            float z  = 1.f / (1.f + __expf(-gz));
            float r  = 1.f / (1.f + __expf(-gr));
            float hh = tanhf(xh + r * gh);
            float hn = z * cur[jbase + tid] + (1.f - z) * hh;
            nxt[jbase + tid] = hn;
            if (t < TT - 1) {
                uint32_t hb = __float_as_uint(hn);
                ST_ASYNC_F32(rem_h[nb][0], hb, rem_bar[t & 1][0]);
                ST_ASYNC_F32(rem_h[nb][1], hb, rem_bar[t & 1][1]);
                ST_ASYNC_F32(rem_h[nb][2], hb, rem_bar[t & 1][2]);
            }
            if (write_seq) srow[(size_t)t * HH + jbase + tid] = hn;
        }
        __syncthreads();  // local nxt slice + red reuse ordering
    }
    if (!write_seq && tid < 64)
        hfinal[batch * HH + jbase + tid] = hsm[((TT & 1) << 8) + jbase + tid];
#undef MV_PHASE
}

// ---------------- Dense: out[32,64] = h2 @ wd + bd ----------------
__global__ void __launch_bounds__(256) dense_kernel(const float* __restrict__ h2,
        const float* __restrict__ wd, const float* __restrict__ bd,
        float* __restrict__ out)
{
    int o = blockIdx.x * 256 + threadIdx.x;
    int b = o >> 6, j = o & 63;
    float s = bd[j];
    for (int k = 0; k < HH; ++k) s += h2[b * HH + k] * wd[k * 64 + j];
    out[o] = s;
}

extern "C" void kernel_launch(void* const* d_in, const int* in_sizes, int n_in,
                              void* d_out, int out_size) {
    const float* x     = (const float*)d_in[0];
    const float* gamma = (const float*)d_in[1];
    const float* beta  = (const float*)d_in[2];
    const float* k1    = (const float*)d_in[3];
    const float* rk1   = (const float*)d_in[4];
    const float* b1    = (const float*)d_in[5];
    const float* k2    = (const float*)d_in[6];
    const float* rk2   = (const float*)d_in[7];
    const float* b2    = (const float*)d_in[8];
    const float* wd    = (const float*)d_in[9];
    const float* bd    = (const float*)d_in[10];
    float* out = (float*)d_out;

    float *xn, *xbuf, *h1, *h2;
    cudaGetSymbolAddress((void**)&xn,   g_xn);
    cudaGetSymbolAddress((void**)&xbuf, g_xb);
    cudaGetSymbolAddress((void**)&h1,   g_h1);
    cudaGetSymbolAddress((void**)&h2,   g_h2);

    ln_kernel<<<MTOT / 8, 256>>>(x, gamma, beta, xn);
    gemm_bias<<<dim3(GG / 128, MTOT / 128), 256>>>(xn, k1, b1, xbuf, MTOT, GG, FF);
    gru_kernel<<<128, 256>>>(xbuf, rk1, b1 + GG, h1, h2, 1);
    gemm_bias<<<dim3(GG / 128, MTOT / 128), 256>>>(h1, k2, b2, xbuf, MTOT, GG, HH);
    gru_kernel<<<128, 256>>>(xbuf, rk2, b2 + GG, h1, h2, 0);
    dense_kernel<<<(BB * 64) / 256, 256>>>(h2, wd, bd, out);
}

// round 8
// speedup vs baseline: 2.0712x; 1.1068x over previous
#include <cuda_runtime.h>
#include <cstdint>
#include <math.h>

#define BB 32
#define TT 2048
#define FF 64
#define HH 256
#define GG 768
#define MTOT (BB*TT)

typedef unsigned long long u64;

// scratch (static device arrays: the sanctioned no-alloc workaround)
__device__ float g_xn[(size_t)MTOT*FF];
__device__ float g_xb[(size_t)MTOT*GG];
__device__ float g_h1[(size_t)MTOT*HH];
__device__ float g_h2[BB*HH];

__device__ __forceinline__ u64 ffma2(u64 a, u64 b, u64 c) {
    u64 d;
    asm("fma.rn.f32x2 %0, %1, %2, %3;" : "=l"(d) : "l"(a), "l"(b), "l"(c));
    return d;
}
__device__ __forceinline__ u64 addf2(u64 a, u64 b) {
    u64 d;
    asm("add.rn.f32x2 %0, %1, %2;" : "=l"(d) : "l"(a), "l"(b));
    return d;
}
__device__ __forceinline__ u64 pack2(float x, float y) {
    u64 d;
    asm("mov.b64 %0, {%1, %2};" : "=l"(d) : "f"(x), "f"(y));
    return d;
}
__device__ __forceinline__ void unpack2(u64 v, float& lo, float& hi) {
    asm("mov.b64 {%0, %1}, %2;" : "=f"(lo), "=f"(hi) : "l"(v));
}
__device__ __forceinline__ uint32_t smem_u32(const void* p) {
    return (uint32_t)__cvta_generic_to_shared(p);
}

#define MBAR_INIT(addr, cnt) \
    asm volatile("mbarrier.init.shared.b64 [%0], %1;" :: "r"(addr), "r"(cnt) : "memory")
#define MBAR_EXPECT_TX(addr, bytes) \
    asm volatile("mbarrier.arrive.expect_tx.shared.b64 _, [%0], %1;" :: "r"(addr), "r"(bytes) : "memory")
#define MBAR_WAIT_PARITY(addr, par) do { \
    uint32_t _done = 0; \
    while (!_done) { \
        asm volatile("{\n\t.reg .pred P;\n\t" \
            "mbarrier.try_wait.parity.acquire.cta.shared::cta.b64 P, [%1], %2, 0x989680;\n\t" \
            "selp.b32 %0, 1, 0, P;\n\t}" \
            : "=r"(_done) : "r"(addr), "r"(par) : "memory"); \
    } } while (0)
#define ST_ASYNC_F32(raddr, val, rbar) \
    asm volatile("st.async.shared::cluster.mbarrier::complete_tx::bytes.b32 [%0], %1, [%2];" \
        :: "r"(raddr), "r"(val), "r"(rbar) : "memory")

// ---------------- LayerNorm: one warp per 64-feature row ----------------
__global__ void __launch_bounds__(256) ln_kernel(const float* __restrict__ x,
        const float* __restrict__ gamma, const float* __restrict__ beta,
        float* __restrict__ xn)
{
    int row  = blockIdx.x * 8 + (threadIdx.x >> 5);
    int lane = threadIdx.x & 31;
    const float* xr = x + (size_t)row * FF;
    float v0 = xr[lane], v1 = xr[lane + 32];
    float s = v0 + v1;
    #pragma unroll
    for (int o = 16; o > 0; o >>= 1) s += __shfl_xor_sync(0xffffffffu, s, o);
    float mu = s * (1.f / FF);
    float d0 = v0 - mu, d1 = v1 - mu;
    float q = d0 * d0 + d1 * d1;
    #pragma unroll
    for (int o = 16; o > 0; o >>= 1) q += __shfl_xor_sync(0xffffffffu, q, o);
    float inv = rsqrtf(q * (1.f / FF) + 1e-3f);
    float* orow = xn + (size_t)row * FF;
    orow[lane]      = d0 * inv * gamma[lane]      + beta[lane];
    orow[lane + 32] = d1 * inv * gamma[lane + 32] + beta[lane + 32];
}

// ---- GEMM + bias: 128x128 tile, BK=16, 8x8 microtile, f32x2 FMA,
// ---- double-buffered SMEM (1 syncthreads per k-iter, prefetch in regs) ----
__global__ void __launch_bounds__(256) gemm_bias(const float* __restrict__ A,
        const float* __restrict__ B, const float* __restrict__ bias,
        float* __restrict__ C, int M, int N, int K)
{
    __shared__ __align__(16) float As[2][16][132];
    __shared__ __align__(16) float Bs[2][16][128];
    const int tid = threadIdx.x;
    const int bn = blockIdx.x * 128, bm = blockIdx.y * 128;
    const int arow = tid >> 2, ak = (tid & 3) << 2;
    const int brow = tid >> 4, bc = (tid & 15) << 3;
    const int rm   = (tid >> 4) << 3, rn = (tid & 15) << 3;

    u64 c2[8][4];
    #pragma unroll
    for (int i = 0; i < 8; ++i)
        #pragma unroll
        for (int j = 0; j < 4; ++j) c2[i][j] = 0ull;

    const float* Ap0 = A + (size_t)(bm + arow) * K + ak;
    const float* Ap1 = A + (size_t)(bm + arow + 64) * K + ak;
    const float* Bp0 = B + (size_t)brow * N + bn + bc;

    // prologue: load k0=0 tile
    float4 a0 = *(const float4*)(Ap0);
    float4 a1 = *(const float4*)(Ap1);
    float4 b0 = *(const float4*)(Bp0);
    float4 b1 = *(const float4*)(Bp0 + 4);
    {
        As[0][ak + 0][arow] = a0.x; As[0][ak + 1][arow] = a0.y;
        As[0][ak + 2][arow] = a0.z; As[0][ak + 3][arow] = a0.w;
        As[0][ak + 0][arow + 64] = a1.x; As[0][ak + 1][arow + 64] = a1.y;
        As[0][ak + 2][arow + 64] = a1.z; As[0][ak + 3][arow + 64] = a1.w;
        *(float4*)&Bs[0][brow][bc]     = b0;
        *(float4*)&Bs[0][brow][bc + 4] = b1;
    }
    __syncthreads();

    for (int k0 = 0; k0 < K; k0 += 16) {
        const int cur = (k0 >> 4) & 1, nxt = cur ^ 1;
        const bool more = (k0 + 16) < K;
        if (more) {
            a0 = *(const float4*)(Ap0 + k0 + 16);
            a1 = *(const float4*)(Ap1 + k0 + 16);
            b0 = *(const float4*)(Bp0 + (size_t)(k0 + 16) * N);
            b1 = *(const float4*)(Bp0 + (size_t)(k0 + 16) * N + 4);
        }
        #pragma unroll
        for (int k = 0; k < 16; ++k) {
            float4 x0 = *(const float4*)&As[cur][k][rm];
            float4 x1 = *(const float4*)&As[cur][k][rm + 4];
            ulonglong2 q0 = *(const ulonglong2*)&Bs[cur][k][rn];
            ulonglong2 q1 = *(const ulonglong2*)&Bs[cur][k][rn + 4];
            float am[8] = {x0.x, x0.y, x0.z, x0.w, x1.x, x1.y, x1.z, x1.w};
            #pragma unroll
            for (int i = 0; i < 8; ++i) {
                u64 aa = pack2(am[i], am[i]);
                c2[i][0] = ffma2(aa, q0.x, c2[i][0]);
                c2[i][1] = ffma2(aa, q0.y, c2[i][1]);
                c2[i][2] = ffma2(aa, q1.x, c2[i][2]);
                c2[i][3] = ffma2(aa, q1.y, c2[i][3]);
            }
        }
        if (more) {
            As[nxt][ak + 0][arow] = a0.x; As[nxt][ak + 1][arow] = a0.y;
            As[nxt][ak + 2][arow] = a0.z; As[nxt][ak + 3][arow] = a0.w;
            As[nxt][ak + 0][arow + 64] = a1.x; As[nxt][ak + 1][arow + 64] = a1.y;
            As[nxt][ak + 2][arow + 64] = a1.z; As[nxt][ak + 3][arow + 64] = a1.w;
            *(float4*)&Bs[nxt][brow][bc]     = b0;
            *(float4*)&Bs[nxt][brow][bc + 4] = b1;
            __syncthreads();
        }
    }
    float4 bv0 = *(const float4*)(bias + bn + rn);
    float4 bv1 = *(const float4*)(bias + bn + rn + 4);
    #pragma unroll
    for (int i = 0; i < 8; ++i) {
        float o[8];
        unpack2(c2[i][0], o[0], o[1]);
        unpack2(c2[i][1], o[2], o[3]);
        unpack2(c2[i][2], o[4], o[5]);
        unpack2(c2[i][3], o[6], o[7]);
        float4 w0 = {o[0] + bv0.x, o[1] + bv0.y, o[2] + bv0.z, o[3] + bv0.w};
        float4 w1 = {o[4] + bv1.x, o[5] + bv1.y, o[6] + bv1.z, o[7] + bv1.w};
        float* cp = C + (size_t)(bm + rm + i) * N + bn + rn;
        *(float4*)cp = w0;
        *(float4*)(cp + 4) = w1;
    }
}

// --------- Persistent GRU: 32 clusters x 4 CTAs, 1 cluster/batch ---------
// Register-resident weights (96 u64/thread). Warp w owns k-slice w*8..w*8+8
// of each 64-k phase block; lane l owns column-pair {2l,2l+1} of each gate
// -> 3 packed accumulators, partials reduced once through smem.
// h exchange: st.async DSMEM pushes + 2 parity-alternating tx-mbarriers.
// Tail uses MUFU-based sigmoid/tanh (EX2 + RCP), no div.rn / software tanhf.
__global__ void __launch_bounds__(256, 1) __cluster_dims__(4, 1, 1)
gru_kernel(const float* __restrict__ xb, const float* __restrict__ rk,
           const float* __restrict__ brec, float* __restrict__ seqout,
           float* __restrict__ hfinal, int write_seq)
{
    __shared__ __align__(16) float hsm[512];          // 2 x 256 h double-buffer
    __shared__ __align__(16) u64 red[768];            // [gate][warp][cg] = 3*8*32
    __shared__ float brs[192];                        // [3][64]
    __shared__ __align__(8) u64 mbars[2];             // step-parity tx barriers

    const int tid   = threadIdx.x;
    const int rank  = blockIdx.x & 3;
    const int batch = blockIdx.x >> 2;
    const int jbase = rank * 64;
    const int w     = tid >> 5;     // k-slice within each 64-block
    const int l     = tid & 31;     // column-pair group

    int blk[4];
    #pragma unroll
    for (int p = 0; p < 4; ++p) blk[p] = ((rank + p) & 3) * 64;

    // weights: w2[p*8+kk][g] = rk[blk[p]+w*8+kk][g*256 + jbase + {2l,2l+1}]
    u64 w2[32][3];
    #pragma unroll
    for (int p = 0; p < 4; ++p)
        #pragma unroll
        for (int kk = 0; kk < 8; ++kk) {
            const float* wp = rk + (size_t)(blk[p] + w * 8 + kk) * GG + jbase + 2 * l;
            #pragma unroll
            for (int g = 0; g < 3; ++g) {
                float2 v = *(const float2*)(wp + g * 256);
                w2[p * 8 + kk][g] = pack2(v.x, v.y);
            }
        }

    if (tid < 192) brs[tid] = brec[(tid >> 6) * 256 + jbase + (tid & 63)];
    hsm[tid] = 0.f; hsm[256 + tid] = 0.f;

    uint32_t mb[2] = { smem_u32(&mbars[0]), smem_u32(&mbars[1]) };
    if (tid == 0) { MBAR_INIT(mb[0], 1); MBAR_INIT(mb[1], 1); }

    // remote addresses: rem_h[buffer][peer] for my h element, rem_bar[bar][peer]
    uint32_t rem_h[2][3], rem_bar[2][3];
    if (tid < 64) {
        #pragma unroll
        for (int b = 0; b < 2; ++b) {
            uint32_t lh = smem_u32(hsm + b * 256 + jbase + tid);
            uint32_t lb = mb[b];
            #pragma unroll
            for (int p = 0; p < 3; ++p) {
                uint32_t tr = (uint32_t)((rank + 1 + p) & 3), rh, rb;
                asm("mapa.shared::cluster.u32 %0, %1, %2;" : "=r"(rh) : "r"(lh), "r"(tr));
                asm("mapa.shared::cluster.u32 %0, %1, %2;" : "=r"(rb) : "r"(lb), "r"(tr));
                rem_h[b][p] = rh; rem_bar[b][p] = rb;
            }
        }
    }
    __syncthreads();
    // barriers + zeroed h visible cluster-wide before any st.async
    asm volatile("barrier.cluster.arrive.aligned;" ::: "memory");
    asm volatile("barrier.cluster.wait.aligned;" ::: "memory");
    if (tid == 0) { MBAR_EXPECT_TX(mb[0], 768); MBAR_EXPECT_TX(mb[1], 768); } // steps 0,1

    const float* xrow = xb + (size_t)batch * TT * GG;
    float* srow = seqout + (size_t)batch * TT * HH;

#define MV_PHASE(p) { \
        float4 h4a = *(const float4*)(cur + blk[p] + w * 8); \
        float4 h4b = *(const float4*)(cur + blk[p] + w * 8 + 4); \
        float hv[8] = {h4a.x, h4a.y, h4a.z, h4a.w, h4b.x, h4b.y, h4b.z, h4b.w}; \
        _Pragma("unroll") \
        for (int kk = 0; kk < 8; ++kk) { \
            u64 hp = pack2(hv[kk], hv[kk]); \
            a2[0] = ffma2(hp, w2[(p) * 8 + kk][0], a2[0]); \
            a2[1] = ffma2(hp, w2[(p) * 8 + kk][1], a2[1]); \
            a2[2] = ffma2(hp, w2[(p) * 8 + kk][2], a2[2]); \
        } }

    for (int t = 0; t < TT; ++t) {
        const float* cur = hsm + ((t & 1) << 8);
        float*       nxt = hsm + (((t & 1) ^ 1) << 8);
        const int    nb  = (t & 1) ^ 1;

        float xz = 0.f, xr_ = 0.f, xh = 0.f;
        if (tid < 64) {
            const float* xp = xrow + (size_t)t * GG + jbase + tid;
            xz = __ldg(xp); xr_ = __ldg(xp + 256); xh = __ldg(xp + 512);
        }

        u64 a2[3] = {0ull, 0ull, 0ull};
        // phase 0: own k-block (local writes ordered by last step's syncthreads)
        MV_PHASE(0)
        if (t > 0) {
            // wait for step t-1 pushes: barrier (t-1)&1, phase (t-1)>>1
            MBAR_WAIT_PARITY(mb[(t - 1) & 1], ((t - 1) >> 1) & 1);
            if (tid == 0 && t <= TT - 3) MBAR_EXPECT_TX(mb[(t + 1) & 1], 768);
        }
        MV_PHASE(1)
        MV_PHASE(2)
        MV_PHASE(3)

        red[0 * 256 + w * 32 + l] = a2[0];
        red[1 * 256 + w * 32 + l] = a2[1];
        red[2 * 256 + w * 32 + l] = a2[2];
        __syncthreads();

        if (tid < 64) {
            const int cg = tid >> 1, half = tid & 1;
            u64 s0 = red[cg], s1 = red[256 + cg], s2 = red[512 + cg];
            #pragma unroll
            for (int ww = 1; ww < 8; ++ww) {
                s0 = addf2(s0, red[ww * 32 + cg]);
                s1 = addf2(s1, red[256 + ww * 32 + cg]);
                s2 = addf2(s2, red[512 + ww * 32 + cg]);
            }
            float lo0, hi0, lo1, hi1, lo2, hi2;
            unpack2(s0, lo0, hi0); unpack2(s1, lo1, hi1); unpack2(s2, lo2, hi2);
            float gz = (half ? hi0 : lo0) + brs[tid]       + xz;
            float gr = (half ? hi1 : lo1) + brs[64 + tid]  + xr_;
            float gh = (half ? hi2 : lo2) + brs[128 + tid];
            // sigmoid/tanh via EX2 + approx-RCP (rel err ~2^-22)
            float z  = __fdividef(1.f, 1.f + __expf(-gz));
            float r  = __fdividef(1.f, 1.f + __expf(-gr));
            float u  = xh + r * gh;
            float th = __fdividef(2.f, 1.f + __expf(-2.f * u)) - 1.f;
            float hn = z * cur[jbase + tid] + (1.f - z) * th;
            nxt[jbase + tid] = hn;
            if (t < TT - 1) {
                uint32_t hb = __float_as_uint(hn);
                ST_ASYNC_F32(rem_h[nb][0], hb, rem_bar[t & 1][0]);
                ST_ASYNC_F32(rem_h[nb][1], hb, rem_bar[t & 1][1]);
                ST_ASYNC_F32(rem_h[nb][2], hb, rem_bar[t & 1][2]);
            }
            if (write_seq) srow[(size_t)t * HH + jbase + tid] = hn;
        }
        __syncthreads();  // local nxt slice + red reuse ordering
    }
    if (!write_seq && tid < 64)
        hfinal[batch * HH + jbase + tid] = hsm[((TT & 1) << 8) + jbase + tid];
#undef MV_PHASE
}

// ---------------- Dense: out[32,64] = h2 @ wd + bd ----------------
__global__ void __launch_bounds__(256) dense_kernel(const float* __restrict__ h2,
        const float* __restrict__ wd, const float* __restrict__ bd,
        float* __restrict__ out)
{
    int o = blockIdx.x * 256 + threadIdx.x;
    int b = o >> 6, j = o & 63;
    float s = bd[j];
    for (int k = 0; k < HH; ++k) s += h2[b * HH + k] * wd[k * 64 + j];
    out[o] = s;
}

extern "C" void kernel_launch(void* const* d_in, const int* in_sizes, int n_in,
                              void* d_out, int out_size) {
    const float* x     = (const float*)d_in[0];
    const float* gamma = (const float*)d_in[1];
    const float* beta  = (const float*)d_in[2];
    const float* k1    = (const float*)d_in[3];
    const float* rk1   = (const float*)d_in[4];
    const float* b1    = (const float*)d_in[5];
    const float* k2    = (const float*)d_in[6];
    const float* rk2   = (const float*)d_in[7];
    const float* b2    = (const float*)d_in[8];
    const float* wd    = (const float*)d_in[9];
    const float* bd    = (const float*)d_in[10];
    float* out = (float*)d_out;

    float *xn, *xbuf, *h1, *h2;
    cudaGetSymbolAddress((void**)&xn,   g_xn);
    cudaGetSymbolAddress((void**)&xbuf, g_xb);
    cudaGetSymbolAddress((void**)&h1,   g_h1);
    cudaGetSymbolAddress((void**)&h2,   g_h2);

    ln_kernel<<<MTOT / 8, 256>>>(x, gamma, beta, xn);
    gemm_bias<<<dim3(GG / 128, MTOT / 128), 256>>>(xn, k1, b1, xbuf, MTOT, GG, FF);
    gru_kernel<<<128, 256>>>(xbuf, rk1, b1 + GG, h1, h2, 1);
    gemm_bias<<<dim3(GG / 128, MTOT / 128), 256>>>(h1, k2, b2, xbuf, MTOT, GG, HH);
    gru_kernel<<<128, 256>>>(xbuf, rk2, b2 + GG, h1, h2, 0);
    dense_kernel<<<(BB * 64) / 256, 256>>>(h2, wd, bd, out);
}